// round 14
// baseline (speedup 1.0000x reference)
#include <cuda_runtime.h>
#include <cuda_bf16.h>
#include <cuda_fp16.h>
#include <cstdint>

#define N_NODES 50000
#define E_EDGES 800000
#define F 128
#define CAP 64                   // bucket capacity per node (max degree ~40)
#define HS_STRIDE 136            // bf16 per Hs row; 272B -> ldmatrix conflict-free

// ---- scratch (__device__ globals; allocation-free rule) ----
__device__ int   g_cnt[50176];                    // per-node degree/cursor
__device__ int2  g_ebuf[(size_t)50176 * CAP];     // bucket grid {src, bits(w+1)}
__device__ uint2 g_fh[(size_t)N_NODES * 32];      // feature in fp16: row=32 uint2
__device__ __nv_bfloat16 g_whi[F * F];            // W[n][k] bf16 hi
__device__ __nv_bfloat16 g_wlo[F * F];            // W[n][k] bf16 residual

__device__ __forceinline__ uint32_t smem_u32(const void* p) {
    uint32_t a;
    asm("{ .reg .u64 t; cvta.to.shared.u64 t, %1; cvt.u32.u64 %0, t; }"
        : "=r"(a) : "l"(p));
    return a;
}

// bf16 mma.sync m16n8k16, fp32 accumulate (baseline HMMA, no 'a' feature)
__device__ __forceinline__ void mma16816(float& c0, float& c1, float& c2, float& c3,
                                         uint32_t a0, uint32_t a1, uint32_t a2, uint32_t a3,
                                         uint32_t b0, uint32_t b1) {
    asm volatile(
        "mma.sync.aligned.m16n8k16.row.col.f32.bf16.bf16.f32 "
        "{%0,%1,%2,%3}, {%4,%5,%6,%7}, {%8,%9}, {%0,%1,%2,%3};"
        : "+f"(c0), "+f"(c1), "+f"(c2), "+f"(c3)
        : "r"(a0), "r"(a1), "r"(a2), "r"(a3), "r"(b0), "r"(b1));
}

__device__ __forceinline__ void ldmatrix4(uint32_t& r0, uint32_t& r1,
                                          uint32_t& r2, uint32_t& r3, uint32_t addr) {
    asm volatile("ldmatrix.sync.aligned.m8n8.x4.shared.b16 {%0,%1,%2,%3}, [%4];"
                 : "=r"(r0), "=r"(r1), "=r"(r2), "=r"(r3) : "r"(addr));
}

// fp16-pair FMA into float4 accumulator
__device__ __forceinline__ void hfma4(float w, uint2 v, float4& a) {
    float2 p = __half22float2(*reinterpret_cast<const __half2*>(&v.x));
    float2 q = __half22float2(*reinterpret_cast<const __half2*>(&v.y));
    a.x = fmaf(w, p.x, a.x);
    a.y = fmaf(w, p.y, a.y);
    a.z = fmaf(w, q.x, a.z);
    a.w = fmaf(w, q.y, a.w);
}

// ===================== K1: prep (W bf16 split + zero counts + fp16 feat) ===
__global__ __launch_bounds__(256) void prep_kernel(const float* __restrict__ W,
                                                   const float* __restrict__ feature) {
    int tid = blockIdx.x * blockDim.x + threadIdx.x;
    if (tid < F * F) {
        float w = W[tid];                       // W[n][k] row-major
        __nv_bfloat16 hi = __float2bfloat16(w);
        g_whi[tid] = hi;
        g_wlo[tid] = __float2bfloat16(w - __bfloat162float(hi));
    }
    int stride = gridDim.x * blockDim.x;
    for (int i = tid; i < 50176; i += stride)
        g_cnt[i] = 0;
    const float4* f4 = reinterpret_cast<const float4*>(feature);
    for (int i = tid; i < N_NODES * 32; i += stride) {
        float4 v = f4[i];
        __half2 a = __floats2half2_rn(v.x, v.y);
        __half2 b = __floats2half2_rn(v.z, v.w);
        g_fh[i] = make_uint2(*reinterpret_cast<uint32_t*>(&a),
                             *reinterpret_cast<uint32_t*>(&b));
    }
}

// ===================== K2: single-pass bucket ==============================
__global__ __launch_bounds__(256) void bucket_kernel(
    const float* __restrict__ weight,
    const int*   __restrict__ src,
    const int*   __restrict__ dst)
{
    int e = blockIdx.x * blockDim.x + threadIdx.x;
    if (e >= E_EDGES) return;
    int d = __ldg(dst + e);
    int pos = atomicAdd(&g_cnt[d], 1);
    g_ebuf[((size_t)d << 6) + pos] =
        make_int2(__ldg(src + e), __float_as_int(__ldg(weight + e) + 1.0f));
}

// ===================== K3: fused gather(fp16, MLP=16) + HMMA GEMM ==========
// 256 threads, 64 rows per block, 3 blocks/SM.
// Phase A: warp w gathers rows w*8..w*8+7 with up to 16 loads in flight
//          (one exposed L2 latency for degree<=16 rows), fp32 accumulate,
//          exact fp32 self term, h -> bf16 hi/lo smem.
// Phase B: warp w computes tile rows (w&3)*16, cols (w>>2)*64 via mma.sync:
//          D = Ahi*Bhi + Ahi*Blo + Alo*Bhi (+bias).
__global__ __launch_bounds__(256, 3) void fused_kernel(
    const float* __restrict__ feature,
    const float* __restrict__ selfw,
    const float* __restrict__ bvec,
    float*       __restrict__ out)
{
    __shared__ __nv_bfloat16 Hhi[64 * HS_STRIDE];
    __shared__ __nv_bfloat16 Hlo[64 * HS_STRIDE];

    const int tid  = threadIdx.x;
    const int lane = tid & 31;
    const int warp = tid >> 5;
    const int Rbase = blockIdx.x * 64;
    const float4* f4 = reinterpret_cast<const float4*>(feature);

    // ---------------- Phase A: bucket aggregation -> bf16-split smem -------
#pragma unroll 1
    for (int rr = 0; rr < 8; rr++) {
        int rloc = warp * 8 + rr;
        int r = Rbase + rloc;
        uint2* hrow_hi = reinterpret_cast<uint2*>(Hhi + rloc * HS_STRIDE) + lane;
        uint2* hrow_lo = reinterpret_cast<uint2*>(Hlo + rloc * HS_STRIDE) + lane;

        if (r >= N_NODES) {          // pad rows: zeros
            *hrow_hi = make_uint2(0u, 0u);
            *hrow_lo = make_uint2(0u, 0u);
            continue;
        }
        const int2* elist = g_ebuf + ((size_t)r << 6);
        int end = __ldg(&g_cnt[r]);

        float4 a0 = make_float4(0.f, 0.f, 0.f, 0.f);
        float4 a1 = make_float4(0.f, 0.f, 0.f, 0.f);
        float4 a2 = make_float4(0.f, 0.f, 0.f, 0.f);
        float4 a3 = make_float4(0.f, 0.f, 0.f, 0.f);

        int i = 0;
        // MLP=16 main loop: whole average-degree row in one exposed latency
        for (; i + 16 <= end; i += 16) {
            uint2 v[16];
            float w[16];
#pragma unroll
            for (int q = 0; q < 16; q++) {
                int2 e = elist[i + q];
                w[q] = __int_as_float(e.y);
                v[q] = __ldg(g_fh + ((size_t)e.x << 5) + lane);
            }
#pragma unroll
            for (int q = 0; q < 16; q += 4) {
                hfma4(w[q + 0], v[q + 0], a0);
                hfma4(w[q + 1], v[q + 1], a1);
                hfma4(w[q + 2], v[q + 2], a2);
                hfma4(w[q + 3], v[q + 3], a3);
            }
        }
        if (i + 8 <= end) {
            uint2 v[8];
            float w[8];
#pragma unroll
            for (int q = 0; q < 8; q++) {
                int2 e = elist[i + q];
                w[q] = __int_as_float(e.y);
                v[q] = __ldg(g_fh + ((size_t)e.x << 5) + lane);
            }
#pragma unroll
            for (int q = 0; q < 8; q += 4) {
                hfma4(w[q + 0], v[q + 0], a0);
                hfma4(w[q + 1], v[q + 1], a1);
                hfma4(w[q + 2], v[q + 2], a2);
                hfma4(w[q + 3], v[q + 3], a3);
            }
            i += 8;
        }
        if (i + 4 <= end) {
            uint2 v[4];
            float w[4];
#pragma unroll
            for (int q = 0; q < 4; q++) {
                int2 e = elist[i + q];
                w[q] = __int_as_float(e.y);
                v[q] = __ldg(g_fh + ((size_t)e.x << 5) + lane);
            }
            hfma4(w[0], v[0], a0);
            hfma4(w[1], v[1], a1);
            hfma4(w[2], v[2], a2);
            hfma4(w[3], v[3], a3);
            i += 4;
        }
        if (i + 2 <= end) {
            int2 e0 = elist[i], e1 = elist[i + 1];
            uint2 v0 = __ldg(g_fh + ((size_t)e0.x << 5) + lane);
            uint2 v1 = __ldg(g_fh + ((size_t)e1.x << 5) + lane);
            hfma4(__int_as_float(e0.y), v0, a0);
            hfma4(__int_as_float(e1.y), v1, a1);
            i += 2;
        }
        if (i < end) {
            int2 e0 = elist[i];
            uint2 v0 = __ldg(g_fh + ((size_t)e0.x << 5) + lane);
            hfma4(__int_as_float(e0.y), v0, a2);
        }

        // exact fp32 self term
        float sw = __ldg(selfw + r) + 1.0f;
        float4 fv = __ldg(f4 + r * 32 + lane);
        float hx = fmaf(fv.x, sw, (a0.x + a1.x) + (a2.x + a3.x));
        float hy = fmaf(fv.y, sw, (a0.y + a1.y) + (a2.y + a3.y));
        float hz = fmaf(fv.z, sw, (a0.z + a1.z) + (a2.z + a3.z));
        float hw = fmaf(fv.w, sw, (a0.w + a1.w) + (a2.w + a3.w));

        __nv_bfloat16 bx = __float2bfloat16(hx), by = __float2bfloat16(hy);
        __nv_bfloat16 bz = __float2bfloat16(hz), bw = __float2bfloat16(hw);
        __nv_bfloat16 lx = __float2bfloat16(hx - __bfloat162float(bx));
        __nv_bfloat16 ly = __float2bfloat16(hy - __bfloat162float(by));
        __nv_bfloat16 lz = __float2bfloat16(hz - __bfloat162float(bz));
        __nv_bfloat16 lw = __float2bfloat16(hw - __bfloat162float(bw));

        uint32_t hi01 = ((uint32_t)__bfloat16_as_ushort(by) << 16) | __bfloat16_as_ushort(bx);
        uint32_t hi23 = ((uint32_t)__bfloat16_as_ushort(bw) << 16) | __bfloat16_as_ushort(bz);
        uint32_t lo01 = ((uint32_t)__bfloat16_as_ushort(ly) << 16) | __bfloat16_as_ushort(lx);
        uint32_t lo23 = ((uint32_t)__bfloat16_as_ushort(lw) << 16) | __bfloat16_as_ushort(lz);
        *hrow_hi = make_uint2(hi01, hi23);
        *hrow_lo = make_uint2(lo01, lo23);
    }
    __syncthreads();

    // ---------------- Phase B: bf16-split HMMA ------------------------------
    const int rowTile = (warp & 3) * 16;        // 0,16,32,48
    const int colBase = (warp >> 2) * 64;       // 0 or 64
    const int gid = lane >> 2;                  // 0..7
    const int tig = lane & 3;                   // 0..3

    float acc[8][4];
#pragma unroll
    for (int n = 0; n < 8; n++)
#pragma unroll
        for (int j = 0; j < 4; j++) acc[n][j] = 0.f;

    const int arow = rowTile + (lane & 15);
    const int ahalf = (lane >> 4) * 8;
    const uint32_t ahi_base = smem_u32(Hhi + arow * HS_STRIDE + ahalf);
    const uint32_t alo_base = smem_u32(Hlo + arow * HS_STRIDE + ahalf);

#pragma unroll
    for (int ks = 0; ks < 8; ks++) {            // k-steps of 16
        uint32_t ah0, ah1, ah2, ah3, al0, al1, al2, al3;
        ldmatrix4(ah0, ah1, ah2, ah3, ahi_base + ks * 32);
        ldmatrix4(al0, al1, al2, al3, alo_base + ks * 32);

#pragma unroll
        for (int nt = 0; nt < 8; nt++) {
            int n = colBase + nt * 8 + gid;
            int kb = ks * 16 + tig * 2;
            uint32_t bh0 = *reinterpret_cast<const uint32_t*>(g_whi + n * F + kb);
            uint32_t bh1 = *reinterpret_cast<const uint32_t*>(g_whi + n * F + kb + 8);
            uint32_t bl0 = *reinterpret_cast<const uint32_t*>(g_wlo + n * F + kb);
            uint32_t bl1 = *reinterpret_cast<const uint32_t*>(g_wlo + n * F + kb + 8);
            mma16816(acc[nt][0], acc[nt][1], acc[nt][2], acc[nt][3],
                     ah0, ah1, ah2, ah3, bh0, bh1);
            mma16816(acc[nt][0], acc[nt][1], acc[nt][2], acc[nt][3],
                     ah0, ah1, ah2, ah3, bl0, bl1);
            mma16816(acc[nt][0], acc[nt][1], acc[nt][2], acc[nt][3],
                     al0, al1, al2, al3, bh0, bh1);
        }
    }

    // epilogue: bias + store (C frag: rows gid, gid+8; cols tig*2, tig*2+1)
    const int r0 = Rbase + rowTile + gid;
    const int r1 = r0 + 8;
#pragma unroll
    for (int nt = 0; nt < 8; nt++) {
        int c = colBase + nt * 8 + tig * 2;
        float2 bb = *reinterpret_cast<const float2*>(bvec + c);
        if (r0 < N_NODES) {
            float2 o = make_float2(acc[nt][0] + bb.x, acc[nt][1] + bb.y);
            *reinterpret_cast<float2*>(out + (size_t)r0 * F + c) = o;
        }
        if (r1 < N_NODES) {
            float2 o = make_float2(acc[nt][2] + bb.x, acc[nt][3] + bb.y);
            *reinterpret_cast<float2*>(out + (size_t)r1 * F + c) = o;
        }
    }
}

// ===================== launch ==============================================
extern "C" void kernel_launch(void* const* d_in, const int* in_sizes, int n_in,
                              void* d_out, int out_size)
{
    const float* feature = (const float*)d_in[0];
    const float* selfw   = (const float*)d_in[1];
    const float* weight  = (const float*)d_in[2];
    const int*   src     = (const int*)d_in[3];
    const int*   dst     = (const int*)d_in[4];
    const float* W       = (const float*)d_in[5];
    const float* bvec    = (const float*)d_in[6];
    float*       out     = (float*)d_out;

    const int edge_blocks  = (E_EDGES + 255) / 256;   // 3125
    const int fused_blocks = (N_NODES + 63) / 64;     // 782

    prep_kernel<<<1024, 256>>>(W, feature);
    bucket_kernel<<<edge_blocks, 256>>>(weight, src, dst);
    fused_kernel<<<fused_blocks, 256>>>(feature, selfw, bvec, out);
}

// round 15
// speedup vs baseline: 1.0516x; 1.0516x over previous
#include <cuda_runtime.h>
#include <cuda_bf16.h>
#include <cuda_fp16.h>
#include <cstdint>

#define N_NODES 50000
#define E_EDGES 800000
#define F 128
#define CAP 64                   // bucket capacity per node (max degree ~40)
#define HS_STRIDE 136            // bf16 per Hs row; 272B -> ldmatrix conflict-free
#define FULLM 0xffffffffu

// ---- scratch (__device__ globals; allocation-free rule) ----
__device__ int   g_cnt[50176];                    // per-node degree/cursor
__device__ int2  g_ebuf[(size_t)50176 * CAP];     // bucket grid {src, bits(w+1)}
__device__ uint2 g_fh[(size_t)N_NODES * 32];      // feature in fp16: row=32 uint2
__device__ __nv_bfloat16 g_whi[F * F];            // W[n][k] bf16 hi
__device__ __nv_bfloat16 g_wlo[F * F];            // W[n][k] bf16 residual

__device__ __forceinline__ uint32_t smem_u32(const void* p) {
    uint32_t a;
    asm("{ .reg .u64 t; cvta.to.shared.u64 t, %1; cvt.u32.u64 %0, t; }"
        : "=r"(a) : "l"(p));
    return a;
}

// bf16 mma.sync m16n8k16, fp32 accumulate (baseline HMMA, no 'a' feature)
__device__ __forceinline__ void mma16816(float& c0, float& c1, float& c2, float& c3,
                                         uint32_t a0, uint32_t a1, uint32_t a2, uint32_t a3,
                                         uint32_t b0, uint32_t b1) {
    asm volatile(
        "mma.sync.aligned.m16n8k16.row.col.f32.bf16.bf16.f32 "
        "{%0,%1,%2,%3}, {%4,%5,%6,%7}, {%8,%9}, {%0,%1,%2,%3};"
        : "+f"(c0), "+f"(c1), "+f"(c2), "+f"(c3)
        : "r"(a0), "r"(a1), "r"(a2), "r"(a3), "r"(b0), "r"(b1));
}

__device__ __forceinline__ void ldmatrix4(uint32_t& r0, uint32_t& r1,
                                          uint32_t& r2, uint32_t& r3, uint32_t addr) {
    asm volatile("ldmatrix.sync.aligned.m8n8.x4.shared.b16 {%0,%1,%2,%3}, [%4];"
                 : "=r"(r0), "=r"(r1), "=r"(r2), "=r"(r3) : "r"(addr));
}

// fp16-pair FMA into float4 accumulator
__device__ __forceinline__ void hfma4(float w, uint2 v, float4& a) {
    float2 p = __half22float2(*reinterpret_cast<const __half2*>(&v.x));
    float2 q = __half22float2(*reinterpret_cast<const __half2*>(&v.y));
    a.x = fmaf(w, p.x, a.x);
    a.y = fmaf(w, p.y, a.y);
    a.z = fmaf(w, q.x, a.z);
    a.w = fmaf(w, q.y, a.w);
}

// ===================== K1: prep (W bf16 split + zero counts + fp16 feat) ===
__global__ __launch_bounds__(256) void prep_kernel(const float* __restrict__ W,
                                                   const float* __restrict__ feature) {
    int tid = blockIdx.x * blockDim.x + threadIdx.x;
    if (tid < F * F) {
        float w = W[tid];                       // W[n][k] row-major
        __nv_bfloat16 hi = __float2bfloat16(w);
        g_whi[tid] = hi;
        g_wlo[tid] = __float2bfloat16(w - __bfloat162float(hi));
    }
    int stride = gridDim.x * blockDim.x;
    for (int i = tid; i < 50176; i += stride)
        g_cnt[i] = 0;
    const float4* f4 = reinterpret_cast<const float4*>(feature);
    for (int i = tid; i < N_NODES * 32; i += stride) {
        float4 v = f4[i];
        __half2 a = __floats2half2_rn(v.x, v.y);
        __half2 b = __floats2half2_rn(v.z, v.w);
        g_fh[i] = make_uint2(*reinterpret_cast<uint32_t*>(&a),
                             *reinterpret_cast<uint32_t*>(&b));
    }
}

// ===================== K2: single-pass bucket ==============================
__global__ __launch_bounds__(256) void bucket_kernel(
    const float* __restrict__ weight,
    const int*   __restrict__ src,
    const int*   __restrict__ dst)
{
    int e = blockIdx.x * blockDim.x + threadIdx.x;
    if (e >= E_EDGES) return;
    int d = __ldg(dst + e);
    int pos = atomicAdd(&g_cnt[d], 1);
    g_ebuf[((size_t)d << 6) + pos] =
        make_int2(__ldg(src + e), __float_as_int(__ldg(weight + e) + 1.0f));
}

// ===================== K3: fused gather + HMMA GEMM ========================
// 256 threads, 64 rows per block, 3 blocks/SM.
// Phase A: warp w handles rows w*8..w*8+7. Row counts prefetched once per
//          warp; each row's edge list fetched with ONE warp-wide LDG.64
//          (lane l holds edge l, <=32 edges) and distributed via shfl.
//          Feature gathers fp16 (8B/lane), fp32 accumulate, exact fp32 self
//          term, h -> bf16 hi/lo split smem.
// Phase B: warp w computes tile rows (w&3)*16, cols (w>>2)*64 via mma.sync:
//          D = Ahi*Bhi + Ahi*Blo + Alo*Bhi (+bias).
__global__ __launch_bounds__(256, 3) void fused_kernel(
    const float* __restrict__ feature,
    const float* __restrict__ selfw,
    const float* __restrict__ bvec,
    float*       __restrict__ out)
{
    __shared__ __nv_bfloat16 Hhi[64 * HS_STRIDE];
    __shared__ __nv_bfloat16 Hlo[64 * HS_STRIDE];

    const int tid  = threadIdx.x;
    const int lane = tid & 31;
    const int warp = tid >> 5;
    const int Rbase = blockIdx.x * 64;
    const float4* f4 = reinterpret_cast<const float4*>(feature);

    // prefetch this warp's 8 row counts (lanes 0-7, coalesced)
    int mycnt = 0;
    {
        int r = Rbase + warp * 8 + (lane & 7);
        if (lane < 8 && r < N_NODES) mycnt = g_cnt[r];
    }

    // ---------------- Phase A: bucket aggregation -> bf16-split smem -------
#pragma unroll 1
    for (int rr = 0; rr < 8; rr++) {
        int rloc = warp * 8 + rr;
        int r = Rbase + rloc;
        uint2* hrow_hi = reinterpret_cast<uint2*>(Hhi + rloc * HS_STRIDE) + lane;
        uint2* hrow_lo = reinterpret_cast<uint2*>(Hlo + rloc * HS_STRIDE) + lane;

        if (r >= N_NODES) {          // pad rows: zeros
            *hrow_hi = make_uint2(0u, 0u);
            *hrow_lo = make_uint2(0u, 0u);
            continue;
        }
        const int2* elist = g_ebuf + ((size_t)r << 6);
        const int end = __shfl_sync(FULLM, mycnt, rr);
        const int nw = end < 32 ? end : 32;

        // ONE warp-wide coalesced load of the whole edge list (<=32 edges)
        int2 me = make_int2(0, 0);
        if (lane < nw) me = __ldg(elist + lane);

        float4 a0 = make_float4(0.f, 0.f, 0.f, 0.f);
        float4 a1 = make_float4(0.f, 0.f, 0.f, 0.f);
        float4 a2 = make_float4(0.f, 0.f, 0.f, 0.f);
        float4 a3 = make_float4(0.f, 0.f, 0.f, 0.f);

        int i = 0;
        for (; i + 8 <= nw; i += 8) {
            uint2 v[8];
            float w[8];
#pragma unroll
            for (int q = 0; q < 8; q++) {
                int   s = __shfl_sync(FULLM, me.x, i + q);
                w[q] = __int_as_float(__shfl_sync(FULLM, me.y, i + q));
                v[q] = __ldg(g_fh + ((size_t)s << 5) + lane);
            }
            hfma4(w[0], v[0], a0); hfma4(w[1], v[1], a1);
            hfma4(w[2], v[2], a2); hfma4(w[3], v[3], a3);
            hfma4(w[4], v[4], a0); hfma4(w[5], v[5], a1);
            hfma4(w[6], v[6], a2); hfma4(w[7], v[7], a3);
        }
        if (i + 4 <= nw) {
            uint2 v[4];
            float w[4];
#pragma unroll
            for (int q = 0; q < 4; q++) {
                int   s = __shfl_sync(FULLM, me.x, i + q);
                w[q] = __int_as_float(__shfl_sync(FULLM, me.y, i + q));
                v[q] = __ldg(g_fh + ((size_t)s << 5) + lane);
            }
            hfma4(w[0], v[0], a0); hfma4(w[1], v[1], a1);
            hfma4(w[2], v[2], a2); hfma4(w[3], v[3], a3);
            i += 4;
        }
        if (i + 2 <= nw) {
            int   s0 = __shfl_sync(FULLM, me.x, i);
            float w0 = __int_as_float(__shfl_sync(FULLM, me.y, i));
            int   s1 = __shfl_sync(FULLM, me.x, i + 1);
            float w1 = __int_as_float(__shfl_sync(FULLM, me.y, i + 1));
            uint2 v0 = __ldg(g_fh + ((size_t)s0 << 5) + lane);
            uint2 v1 = __ldg(g_fh + ((size_t)s1 << 5) + lane);
            hfma4(w0, v0, a0); hfma4(w1, v1, a1);
            i += 2;
        }
        if (i < nw) {
            int   s0 = __shfl_sync(FULLM, me.x, i);
            float w0 = __int_as_float(__shfl_sync(FULLM, me.y, i));
            uint2 v0 = __ldg(g_fh + ((size_t)s0 << 5) + lane);
            hfma4(w0, v0, a2);
        }
        // rare overflow (degree > 32): scalar broadcast path
        for (int j = 32; j < end; j++) {
            int2 e = __ldg(elist + j);
            uint2 v = __ldg(g_fh + ((size_t)e.x << 5) + lane);
            hfma4(__int_as_float(e.y), v, a3);
        }

        // exact fp32 self term
        float sw = __ldg(selfw + r) + 1.0f;
        float4 fv = __ldg(f4 + r * 32 + lane);
        float hx = fmaf(fv.x, sw, (a0.x + a1.x) + (a2.x + a3.x));
        float hy = fmaf(fv.y, sw, (a0.y + a1.y) + (a2.y + a3.y));
        float hz = fmaf(fv.z, sw, (a0.z + a1.z) + (a2.z + a3.z));
        float hw = fmaf(fv.w, sw, (a0.w + a1.w) + (a2.w + a3.w));

        __nv_bfloat16 bx = __float2bfloat16(hx), by = __float2bfloat16(hy);
        __nv_bfloat16 bz = __float2bfloat16(hz), bw = __float2bfloat16(hw);
        __nv_bfloat16 lx = __float2bfloat16(hx - __bfloat162float(bx));
        __nv_bfloat16 ly = __float2bfloat16(hy - __bfloat162float(by));
        __nv_bfloat16 lz = __float2bfloat16(hz - __bfloat162float(bz));
        __nv_bfloat16 lw = __float2bfloat16(hw - __bfloat162float(bw));

        uint32_t hi01 = ((uint32_t)__bfloat16_as_ushort(by) << 16) | __bfloat16_as_ushort(bx);
        uint32_t hi23 = ((uint32_t)__bfloat16_as_ushort(bw) << 16) | __bfloat16_as_ushort(bz);
        uint32_t lo01 = ((uint32_t)__bfloat16_as_ushort(ly) << 16) | __bfloat16_as_ushort(lx);
        uint32_t lo23 = ((uint32_t)__bfloat16_as_ushort(lw) << 16) | __bfloat16_as_ushort(lz);
        *hrow_hi = make_uint2(hi01, hi23);
        *hrow_lo = make_uint2(lo01, lo23);
    }
    __syncthreads();

    // ---------------- Phase B: bf16-split HMMA ------------------------------
    const int rowTile = (warp & 3) * 16;        // 0,16,32,48
    const int colBase = (warp >> 2) * 64;       // 0 or 64
    const int gid = lane >> 2;                  // 0..7
    const int tig = lane & 3;                   // 0..3

    float acc[8][4];
#pragma unroll
    for (int n = 0; n < 8; n++)
#pragma unroll
        for (int j = 0; j < 4; j++) acc[n][j] = 0.f;

    const int arow = rowTile + (lane & 15);
    const int ahalf = (lane >> 4) * 8;
    const uint32_t ahi_base = smem_u32(Hhi + arow * HS_STRIDE + ahalf);
    const uint32_t alo_base = smem_u32(Hlo + arow * HS_STRIDE + ahalf);

#pragma unroll
    for (int ks = 0; ks < 8; ks++) {            // k-steps of 16
        uint32_t ah0, ah1, ah2, ah3, al0, al1, al2, al3;
        ldmatrix4(ah0, ah1, ah2, ah3, ahi_base + ks * 32);
        ldmatrix4(al0, al1, al2, al3, alo_base + ks * 32);

#pragma unroll
        for (int nt = 0; nt < 8; nt++) {
            int n = colBase + nt * 8 + gid;
            int kb = ks * 16 + tig * 2;
            uint32_t bh0 = *reinterpret_cast<const uint32_t*>(g_whi + n * F + kb);
            uint32_t bh1 = *reinterpret_cast<const uint32_t*>(g_whi + n * F + kb + 8);
            uint32_t bl0 = *reinterpret_cast<const uint32_t*>(g_wlo + n * F + kb);
            uint32_t bl1 = *reinterpret_cast<const uint32_t*>(g_wlo + n * F + kb + 8);
            mma16816(acc[nt][0], acc[nt][1], acc[nt][2], acc[nt][3],
                     ah0, ah1, ah2, ah3, bh0, bh1);
            mma16816(acc[nt][0], acc[nt][1], acc[nt][2], acc[nt][3],
                     ah0, ah1, ah2, ah3, bl0, bl1);
            mma16816(acc[nt][0], acc[nt][1], acc[nt][2], acc[nt][3],
                     al0, al1, al2, al3, bh0, bh1);
        }
    }

    // epilogue: bias + store (C frag: rows gid, gid+8; cols tig*2, tig*2+1)
    const int r0 = Rbase + rowTile + gid;
    const int r1 = r0 + 8;
#pragma unroll
    for (int nt = 0; nt < 8; nt++) {
        int c = colBase + nt * 8 + tig * 2;
        float2 bb = *reinterpret_cast<const float2*>(bvec + c);
        if (r0 < N_NODES) {
            float2 o = make_float2(acc[nt][0] + bb.x, acc[nt][1] + bb.y);
            *reinterpret_cast<float2*>(out + (size_t)r0 * F + c) = o;
        }
        if (r1 < N_NODES) {
            float2 o = make_float2(acc[nt][2] + bb.x, acc[nt][3] + bb.y);
            *reinterpret_cast<float2*>(out + (size_t)r1 * F + c) = o;
        }
    }
}

// ===================== launch ==============================================
extern "C" void kernel_launch(void* const* d_in, const int* in_sizes, int n_in,
                              void* d_out, int out_size)
{
    const float* feature = (const float*)d_in[0];
    const float* selfw   = (const float*)d_in[1];
    const float* weight  = (const float*)d_in[2];
    const int*   src     = (const int*)d_in[3];
    const int*   dst     = (const int*)d_in[4];
    const float* W       = (const float*)d_in[5];
    const float* bvec    = (const float*)d_in[6];
    float*       out     = (float*)d_out;

    const int edge_blocks  = (E_EDGES + 255) / 256;   // 3125
    const int fused_blocks = (N_NODES + 63) / 64;     // 782

    prep_kernel<<<1024, 256>>>(W, feature);
    bucket_kernel<<<edge_blocks, 256>>>(weight, src, dst);
    fused_kernel<<<fused_blocks, 256>>>(feature, selfw, bvec, out);
}

// round 16
// speedup vs baseline: 1.0763x; 1.0234x over previous
#include <cuda_runtime.h>
#include <cuda_bf16.h>
#include <cuda_fp16.h>
#include <cstdint>

#define N_NODES 50000
#define E_EDGES 800000
#define F 128
#define CAP 64                   // bucket capacity per node (max degree ~40)
#define HS_STRIDE 136            // bf16 per Hs row; 272B -> ldmatrix conflict-free
#define FULLM 0xffffffffu

// ---- scratch (__device__ globals; allocation-free rule) ----
// g_cnt is zero-initialized at module load; fused_kernel re-zeroes the
// counters it consumed at the end of each launch, so every kernel_launch
// call starts from zeros without a dedicated zeroing kernel.
__device__ int   g_cnt[50176];                    // per-node degree/cursor
__device__ int2  g_ebuf[(size_t)50176 * CAP];     // bucket grid {src, bits(w+1)}
__device__ uint2 g_fh[(size_t)N_NODES * 32];      // feature in fp16: row=32 uint2
__device__ __nv_bfloat16 g_whi[F * F];            // W[n][k] bf16 hi
__device__ __nv_bfloat16 g_wlo[F * F];            // W[n][k] bf16 residual

__device__ __forceinline__ uint32_t smem_u32(const void* p) {
    uint32_t a;
    asm("{ .reg .u64 t; cvta.to.shared.u64 t, %1; cvt.u32.u64 %0, t; }"
        : "=r"(a) : "l"(p));
    return a;
}

// bf16 mma.sync m16n8k16, fp32 accumulate (baseline HMMA, no 'a' feature)
__device__ __forceinline__ void mma16816(float& c0, float& c1, float& c2, float& c3,
                                         uint32_t a0, uint32_t a1, uint32_t a2, uint32_t a3,
                                         uint32_t b0, uint32_t b1) {
    asm volatile(
        "mma.sync.aligned.m16n8k16.row.col.f32.bf16.bf16.f32 "
        "{%0,%1,%2,%3}, {%4,%5,%6,%7}, {%8,%9}, {%0,%1,%2,%3};"
        : "+f"(c0), "+f"(c1), "+f"(c2), "+f"(c3)
        : "r"(a0), "r"(a1), "r"(a2), "r"(a3), "r"(b0), "r"(b1));
}

__device__ __forceinline__ void ldmatrix4(uint32_t& r0, uint32_t& r1,
                                          uint32_t& r2, uint32_t& r3, uint32_t addr) {
    asm volatile("ldmatrix.sync.aligned.m8n8.x4.shared.b16 {%0,%1,%2,%3}, [%4];"
                 : "=r"(r0), "=r"(r1), "=r"(r2), "=r"(r3) : "r"(addr));
}

// fp16-pair FMA into float4 accumulator
__device__ __forceinline__ void hfma4(float w, uint2 v, float4& a) {
    float2 p = __half22float2(*reinterpret_cast<const __half2*>(&v.x));
    float2 q = __half22float2(*reinterpret_cast<const __half2*>(&v.y));
    a.x = fmaf(w, p.x, a.x);
    a.y = fmaf(w, p.y, a.y);
    a.z = fmaf(w, q.x, a.z);
    a.w = fmaf(w, q.y, a.w);
}

// ===================== K1: bucket + W split + fp16 feature (merged) ========
// 800000 threads. Edge bucketing is atomic-latency bound (issue ~4%), so the
// W-split and fp32->fp16 feature conversion ride along in idle issue slots.
__global__ __launch_bounds__(256) void bucket_prep_kernel(
    const float* __restrict__ W,
    const float* __restrict__ feature,
    const float* __restrict__ weight,
    const int*   __restrict__ src,
    const int*   __restrict__ dst)
{
    int tid = blockIdx.x * blockDim.x + threadIdx.x;

    // W bf16 split (first 16384 threads)
    if (tid < F * F) {
        float w = W[tid];                       // W[n][k] row-major
        __nv_bfloat16 hi = __float2bfloat16(w);
        g_whi[tid] = hi;
        g_wlo[tid] = __float2bfloat16(w - __bfloat162float(hi));
    }

    // feature fp32 -> fp16 plane (1.6M uint2, 2 per thread)
    const float4* f4 = reinterpret_cast<const float4*>(feature);
#pragma unroll
    for (int q = 0; q < 2; q++) {
        int i = tid + q * (E_EDGES);            // stride = total threads
        if (i < N_NODES * 32) {
            float4 v = f4[i];
            __half2 a = __floats2half2_rn(v.x, v.y);
            __half2 b = __floats2half2_rn(v.z, v.w);
            g_fh[i] = make_uint2(*reinterpret_cast<uint32_t*>(&a),
                                 *reinterpret_cast<uint32_t*>(&b));
        }
    }

    // edge bucketing
    if (tid < E_EDGES) {
        int d = __ldg(dst + tid);
        int pos = atomicAdd(&g_cnt[d], 1);
        g_ebuf[((size_t)d << 6) + pos] =
            make_int2(__ldg(src + tid), __float_as_int(__ldg(weight + tid) + 1.0f));
    }
}

// ===================== K2: fused gather + HMMA GEMM ========================
// 256 threads, 64 rows per block, 3 blocks/SM.
// Phase A: warp w handles rows w*8..w*8+7. Row counts prefetched once;
//          row rr+1's edge list (one warp-wide LDG.64) is prefetched while
//          row rr's gathers/FMAs run (software pipeline depth 1).
//          fp16 gathers (8B/lane), fp32 accumulate, exact fp32 self term,
//          h -> bf16 hi/lo split smem. g_cnt re-zeroed after Phase A.
// Phase B: warp w computes tile rows (w&3)*16, cols (w>>2)*64 via mma.sync:
//          D = Ahi*Bhi + Ahi*Blo + Alo*Bhi (+bias).
__global__ __launch_bounds__(256, 3) void fused_kernel(
    const float* __restrict__ feature,
    const float* __restrict__ selfw,
    const float* __restrict__ bvec,
    float*       __restrict__ out)
{
    __shared__ __nv_bfloat16 Hhi[64 * HS_STRIDE];
    __shared__ __nv_bfloat16 Hlo[64 * HS_STRIDE];

    const int tid  = threadIdx.x;
    const int lane = tid & 31;
    const int warp = tid >> 5;
    const int Rbase = blockIdx.x * 64;
    const float4* f4 = reinterpret_cast<const float4*>(feature);

    // prefetch this warp's 8 row counts (lanes 0-7, coalesced)
    int mycnt = 0;
    {
        int r = Rbase + warp * 8 + (lane & 7);
        if (lane < 8 && r < N_NODES) mycnt = g_cnt[r];
    }

    // preload row 0's edge list (warp-wide LDG.64)
    int2 me = make_int2(0, 0);
    {
        int r0 = Rbase + warp * 8;
        int c0 = __shfl_sync(FULLM, mycnt, 0);
        int n0 = c0 < 32 ? c0 : 32;
        if (r0 < N_NODES && lane < n0)
            me = __ldg(g_ebuf + ((size_t)r0 << 6) + lane);
    }

    // ---------------- Phase A: bucket aggregation -> bf16-split smem -------
#pragma unroll 1
    for (int rr = 0; rr < 8; rr++) {
        int rloc = warp * 8 + rr;
        int r = Rbase + rloc;
        uint2* hrow_hi = reinterpret_cast<uint2*>(Hhi + rloc * HS_STRIDE) + lane;
        uint2* hrow_lo = reinterpret_cast<uint2*>(Hlo + rloc * HS_STRIDE) + lane;

        const int2 mine = me;
        const int end = __shfl_sync(FULLM, mycnt, rr);
        const int nw = end < 32 ? end : 32;

        // prefetch next row's edge list while this row's gathers run
        if (rr < 7) {
            int rn = Rbase + rloc + 1;
            int cn = __shfl_sync(FULLM, mycnt, rr + 1);
            int nn = cn < 32 ? cn : 32;
            me = make_int2(0, 0);
            if (rn < N_NODES && lane < nn)
                me = __ldg(g_ebuf + ((size_t)rn << 6) + lane);
        }

        if (r >= N_NODES) {          // pad rows: zeros
            *hrow_hi = make_uint2(0u, 0u);
            *hrow_lo = make_uint2(0u, 0u);
            continue;
        }

        float4 a0 = make_float4(0.f, 0.f, 0.f, 0.f);
        float4 a1 = make_float4(0.f, 0.f, 0.f, 0.f);
        float4 a2 = make_float4(0.f, 0.f, 0.f, 0.f);
        float4 a3 = make_float4(0.f, 0.f, 0.f, 0.f);

        int i = 0;
        for (; i + 8 <= nw; i += 8) {
            uint2 v[8];
            float w[8];
#pragma unroll
            for (int q = 0; q < 8; q++) {
                int   s = __shfl_sync(FULLM, mine.x, i + q);
                w[q] = __int_as_float(__shfl_sync(FULLM, mine.y, i + q));
                v[q] = __ldg(g_fh + ((size_t)s << 5) + lane);
            }
            hfma4(w[0], v[0], a0); hfma4(w[1], v[1], a1);
            hfma4(w[2], v[2], a2); hfma4(w[3], v[3], a3);
            hfma4(w[4], v[4], a0); hfma4(w[5], v[5], a1);
            hfma4(w[6], v[6], a2); hfma4(w[7], v[7], a3);
        }
        if (i + 4 <= nw) {
            uint2 v[4];
            float w[4];
#pragma unroll
            for (int q = 0; q < 4; q++) {
                int   s = __shfl_sync(FULLM, mine.x, i + q);
                w[q] = __int_as_float(__shfl_sync(FULLM, mine.y, i + q));
                v[q] = __ldg(g_fh + ((size_t)s << 5) + lane);
            }
            hfma4(w[0], v[0], a0); hfma4(w[1], v[1], a1);
            hfma4(w[2], v[2], a2); hfma4(w[3], v[3], a3);
            i += 4;
        }
        if (i + 2 <= nw) {
            int   s0 = __shfl_sync(FULLM, mine.x, i);
            float w0 = __int_as_float(__shfl_sync(FULLM, mine.y, i));
            int   s1 = __shfl_sync(FULLM, mine.x, i + 1);
            float w1 = __int_as_float(__shfl_sync(FULLM, mine.y, i + 1));
            uint2 v0 = __ldg(g_fh + ((size_t)s0 << 5) + lane);
            uint2 v1 = __ldg(g_fh + ((size_t)s1 << 5) + lane);
            hfma4(w0, v0, a0); hfma4(w1, v1, a1);
            i += 2;
        }
        if (i < nw) {
            int   s0 = __shfl_sync(FULLM, mine.x, i);
            float w0 = __int_as_float(__shfl_sync(FULLM, mine.y, i));
            uint2 v0 = __ldg(g_fh + ((size_t)s0 << 5) + lane);
            hfma4(w0, v0, a2);
        }
        // rare overflow (degree > 32): scalar broadcast path
        for (int j = 32; j < end; j++) {
            int2 e = __ldg(g_ebuf + ((size_t)r << 6) + j);
            uint2 v = __ldg(g_fh + ((size_t)e.x << 5) + lane);
            hfma4(__int_as_float(e.y), v, a3);
        }

        // exact fp32 self term
        float sw = __ldg(selfw + r) + 1.0f;
        float4 fv = __ldg(f4 + r * 32 + lane);
        float hx = fmaf(fv.x, sw, (a0.x + a1.x) + (a2.x + a3.x));
        float hy = fmaf(fv.y, sw, (a0.y + a1.y) + (a2.y + a3.y));
        float hz = fmaf(fv.z, sw, (a0.z + a1.z) + (a2.z + a3.z));
        float hw = fmaf(fv.w, sw, (a0.w + a1.w) + (a2.w + a3.w));

        __nv_bfloat16 bx = __float2bfloat16(hx), by = __float2bfloat16(hy);
        __nv_bfloat16 bz = __float2bfloat16(hz), bw = __float2bfloat16(hw);
        __nv_bfloat16 lx = __float2bfloat16(hx - __bfloat162float(bx));
        __nv_bfloat16 ly = __float2bfloat16(hy - __bfloat162float(by));
        __nv_bfloat16 lz = __float2bfloat16(hz - __bfloat162float(bz));
        __nv_bfloat16 lw = __float2bfloat16(hw - __bfloat162float(bw));

        uint32_t hi01 = ((uint32_t)__bfloat16_as_ushort(by) << 16) | __bfloat16_as_ushort(bx);
        uint32_t hi23 = ((uint32_t)__bfloat16_as_ushort(bw) << 16) | __bfloat16_as_ushort(bz);
        uint32_t lo01 = ((uint32_t)__bfloat16_as_ushort(ly) << 16) | __bfloat16_as_ushort(lx);
        uint32_t lo23 = ((uint32_t)__bfloat16_as_ushort(lw) << 16) | __bfloat16_as_ushort(lz);
        *hrow_hi = make_uint2(hi01, hi23);
        *hrow_lo = make_uint2(lo01, lo23);
    }
    __syncthreads();

    // reset this block's counters for the next launch (all warps have read
    // their counts before the barrier above)
    if (warp == 0) {
        int r = Rbase + lane;
        if (r < N_NODES) g_cnt[r] = 0;
        r += 32;
        if (r < N_NODES) g_cnt[r] = 0;
    }

    // ---------------- Phase B: bf16-split HMMA ------------------------------
    const int rowTile = (warp & 3) * 16;        // 0,16,32,48
    const int colBase = (warp >> 2) * 64;       // 0 or 64
    const int gid = lane >> 2;                  // 0..7
    const int tig = lane & 3;                   // 0..3

    float acc[8][4];
#pragma unroll
    for (int n = 0; n < 8; n++)
#pragma unroll
        for (int j = 0; j < 4; j++) acc[n][j] = 0.f;

    const int arow = rowTile + (lane & 15);
    const int ahalf = (lane >> 4) * 8;
    const uint32_t ahi_base = smem_u32(Hhi + arow * HS_STRIDE + ahalf);
    const uint32_t alo_base = smem_u32(Hlo + arow * HS_STRIDE + ahalf);

#pragma unroll
    for (int ks = 0; ks < 8; ks++) {            // k-steps of 16
        uint32_t ah0, ah1, ah2, ah3, al0, al1, al2, al3;
        ldmatrix4(ah0, ah1, ah2, ah3, ahi_base + ks * 32);
        ldmatrix4(al0, al1, al2, al3, alo_base + ks * 32);

#pragma unroll
        for (int nt = 0; nt < 8; nt++) {
            int n = colBase + nt * 8 + gid;
            int kb = ks * 16 + tig * 2;
            uint32_t bh0 = *reinterpret_cast<const uint32_t*>(g_whi + n * F + kb);
            uint32_t bh1 = *reinterpret_cast<const uint32_t*>(g_whi + n * F + kb + 8);
            uint32_t bl0 = *reinterpret_cast<const uint32_t*>(g_wlo + n * F + kb);
            uint32_t bl1 = *reinterpret_cast<const uint32_t*>(g_wlo + n * F + kb + 8);
            mma16816(acc[nt][0], acc[nt][1], acc[nt][2], acc[nt][3],
                     ah0, ah1, ah2, ah3, bh0, bh1);
            mma16816(acc[nt][0], acc[nt][1], acc[nt][2], acc[nt][3],
                     ah0, ah1, ah2, ah3, bl0, bl1);
            mma16816(acc[nt][0], acc[nt][1], acc[nt][2], acc[nt][3],
                     al0, al1, al2, al3, bh0, bh1);
        }
    }

    // epilogue: bias + store (C frag: rows gid, gid+8; cols tig*2, tig*2+1)
    const int r0 = Rbase + rowTile + gid;
    const int r1 = r0 + 8;
#pragma unroll
    for (int nt = 0; nt < 8; nt++) {
        int c = colBase + nt * 8 + tig * 2;
        float2 bb = *reinterpret_cast<const float2*>(bvec + c);
        if (r0 < N_NODES) {
            float2 o = make_float2(acc[nt][0] + bb.x, acc[nt][1] + bb.y);
            *reinterpret_cast<float2*>(out + (size_t)r0 * F + c) = o;
        }
        if (r1 < N_NODES) {
            float2 o = make_float2(acc[nt][2] + bb.x, acc[nt][3] + bb.y);
            *reinterpret_cast<float2*>(out + (size_t)r1 * F + c) = o;
        }
    }
}

// ===================== launch ==============================================
extern "C" void kernel_launch(void* const* d_in, const int* in_sizes, int n_in,
                              void* d_out, int out_size)
{
    const float* feature = (const float*)d_in[0];
    const float* selfw   = (const float*)d_in[1];
    const float* weight  = (const float*)d_in[2];
    const int*   src     = (const int*)d_in[3];
    const int*   dst     = (const int*)d_in[4];
    const float* W       = (const float*)d_in[5];
    const float* bvec    = (const float*)d_in[6];
    float*       out     = (float*)d_out;

    const int edge_blocks  = (E_EDGES + 255) / 256;   // 3125
    const int fused_blocks = (N_NODES + 63) / 64;     // 782

    bucket_prep_kernel<<<edge_blocks, 256>>>(W, feature, weight, src, dst);
    fused_kernel<<<fused_blocks, 256>>>(feature, selfw, bvec, out);
}

// round 17
// speedup vs baseline: 1.7849x; 1.6584x over previous
#include <cuda_runtime.h>
#include <cuda_bf16.h>
#include <cuda_fp16.h>
#include <cstdint>

#define N_NODES 50000
#define E_EDGES 800000
#define F 128
#define CAP 64                   // bucket capacity per node (max degree ~40)
#define HS_STRIDE 136            // bf16 per Hs row; 272B -> ldmatrix conflict-free
#define FULLM 0xffffffffu

// ---- scratch (__device__ globals; allocation-free rule) ----
// g_cnt is zero-initialized at module load; fused_kernel re-zeroes the
// counters it consumed, so every launch starts from zeros.
__device__ int   g_cnt[50176];                    // per-node degree/cursor
__device__ int2  g_ebuf[(size_t)50176 * CAP];     // bucket grid {src, bits(w+1)}
__device__ uint2 g_fh[(size_t)N_NODES * 32];      // feature fp16: row = 32 uint2
// W pre-packed into m16n8k16 B-fragment layout:
//   index = (ks*16 + ntg)*32 + lane, lane holds {b0, b1} for
//   n = ntg*8 + lane/4, k = ks*16 + (lane%4)*2 (+8 for b1).
__device__ uint2 g_wfh[4096];                     // bf16 hi fragments
__device__ uint2 g_wfl[4096];                     // bf16 residual fragments

__device__ __forceinline__ uint32_t smem_u32(const void* p) {
    uint32_t a;
    asm("{ .reg .u64 t; cvta.to.shared.u64 t, %1; cvt.u32.u64 %0, t; }"
        : "=r"(a) : "l"(p));
    return a;
}

// bf16 mma.sync m16n8k16, fp32 accumulate (baseline HMMA, no 'a' feature)
__device__ __forceinline__ void mma16816(float& c0, float& c1, float& c2, float& c3,
                                         uint32_t a0, uint32_t a1, uint32_t a2, uint32_t a3,
                                         uint32_t b0, uint32_t b1) {
    asm volatile(
        "mma.sync.aligned.m16n8k16.row.col.f32.bf16.bf16.f32 "
        "{%0,%1,%2,%3}, {%4,%5,%6,%7}, {%8,%9}, {%0,%1,%2,%3};"
        : "+f"(c0), "+f"(c1), "+f"(c2), "+f"(c3)
        : "r"(a0), "r"(a1), "r"(a2), "r"(a3), "r"(b0), "r"(b1));
}

__device__ __forceinline__ void ldmatrix4(uint32_t& r0, uint32_t& r1,
                                          uint32_t& r2, uint32_t& r3, uint32_t addr) {
    asm volatile("ldmatrix.sync.aligned.m8n8.x4.shared.b16 {%0,%1,%2,%3}, [%4];"
                 : "=r"(r0), "=r"(r1), "=r"(r2), "=r"(r3) : "r"(addr));
}

// fp16-pair FMA into float4 accumulator
__device__ __forceinline__ void hfma4(float w, uint2 v, float4& a) {
    float2 p = __half22float2(*reinterpret_cast<const __half2*>(&v.x));
    float2 q = __half22float2(*reinterpret_cast<const __half2*>(&v.y));
    a.x = fmaf(w, p.x, a.x);
    a.y = fmaf(w, p.y, a.y);
    a.z = fmaf(w, q.x, a.z);
    a.w = fmaf(w, q.y, a.w);
}

__device__ __forceinline__ uint32_t pack_bf16(float lo, float hi) {
    __nv_bfloat16 l = __float2bfloat16(lo), h = __float2bfloat16(hi);
    return ((uint32_t)__bfloat16_as_ushort(h) << 16) | __bfloat16_as_ushort(l);
}

// ===================== K1: bucket + W fragment pack + fp16 feature =========
__global__ __launch_bounds__(256) void bucket_prep_kernel(
    const float* __restrict__ W,
    const float* __restrict__ feature,
    const float* __restrict__ weight,
    const int*   __restrict__ src,
    const int*   __restrict__ dst)
{
    int tid = blockIdx.x * blockDim.x + threadIdx.x;

    // W -> MMA fragment layout, bf16 hi + residual (4096 threads)
    if (tid < 4096) {
        int lane = tid & 31;
        int ntg  = (tid >> 5) & 15;
        int ks   = tid >> 9;                    // 0..7
        int n = ntg * 8 + (lane >> 2);
        int k = ks * 16 + (lane & 3) * 2;
        float w00 = W[n * F + k],     w01 = W[n * F + k + 1];
        float w10 = W[n * F + k + 8], w11 = W[n * F + k + 9];
        float h00 = __bfloat162float(__float2bfloat16(w00));
        float h01 = __bfloat162float(__float2bfloat16(w01));
        float h10 = __bfloat162float(__float2bfloat16(w10));
        float h11 = __bfloat162float(__float2bfloat16(w11));
        g_wfh[tid] = make_uint2(pack_bf16(h00, h01), pack_bf16(h10, h11));
        g_wfl[tid] = make_uint2(pack_bf16(w00 - h00, w01 - h01),
                                pack_bf16(w10 - h10, w11 - h11));
    }

    // feature fp32 -> fp16 plane (1.6M uint2, 2 per thread)
    const float4* f4 = reinterpret_cast<const float4*>(feature);
#pragma unroll
    for (int q = 0; q < 2; q++) {
        int i = tid + q * (E_EDGES);
        if (i < N_NODES * 32) {
            float4 v = f4[i];
            __half2 a = __floats2half2_rn(v.x, v.y);
            __half2 b = __floats2half2_rn(v.z, v.w);
            g_fh[i] = make_uint2(*reinterpret_cast<uint32_t*>(&a),
                                 *reinterpret_cast<uint32_t*>(&b));
        }
    }

    // edge bucketing
    if (tid < E_EDGES) {
        int d = __ldg(dst + tid);
        int pos = atomicAdd(&g_cnt[d], 1);
        g_ebuf[((size_t)d << 6) + pos] =
            make_int2(__ldg(src + tid), __float_as_int(__ldg(weight + tid) + 1.0f));
    }
}

// ===================== K2: fused gather + HMMA GEMM ========================
__global__ __launch_bounds__(256, 3) void fused_kernel(
    const float* __restrict__ feature,
    const float* __restrict__ selfw,
    const float* __restrict__ bvec,
    float*       __restrict__ out)
{
    __shared__ __nv_bfloat16 Hhi[64 * HS_STRIDE];
    __shared__ __nv_bfloat16 Hlo[64 * HS_STRIDE];

    const int tid  = threadIdx.x;
    const int lane = tid & 31;
    const int warp = tid >> 5;
    const int Rbase = blockIdx.x * 64;
    const float4* f4 = reinterpret_cast<const float4*>(feature);

    // prefetch this warp's 8 row counts (lanes 0-7, coalesced)
    int mycnt = 0;
    {
        int r = Rbase + warp * 8 + (lane & 7);
        if (lane < 8 && r < N_NODES) mycnt = g_cnt[r];
    }

    // preload row 0's edge list (warp-wide LDG.64)
    int2 me = make_int2(0, 0);
    {
        int r0 = Rbase + warp * 8;
        int c0 = __shfl_sync(FULLM, mycnt, 0);
        int n0 = c0 < 32 ? c0 : 32;
        if (r0 < N_NODES && lane < n0)
            me = __ldg(g_ebuf + ((size_t)r0 << 6) + lane);
    }

    // ---------------- Phase A: bucket aggregation -> bf16-split smem -------
#pragma unroll 1
    for (int rr = 0; rr < 8; rr++) {
        int rloc = warp * 8 + rr;
        int r = Rbase + rloc;
        uint2* hrow_hi = reinterpret_cast<uint2*>(Hhi + rloc * HS_STRIDE) + lane;
        uint2* hrow_lo = reinterpret_cast<uint2*>(Hlo + rloc * HS_STRIDE) + lane;

        const int2 mine = me;
        const int end = __shfl_sync(FULLM, mycnt, rr);
        const int nw = end < 32 ? end : 32;

        // prefetch next row's edge list while this row's gathers run
        if (rr < 7) {
            int rn = Rbase + rloc + 1;
            int cn = __shfl_sync(FULLM, mycnt, rr + 1);
            int nn = cn < 32 ? cn : 32;
            me = make_int2(0, 0);
            if (rn < N_NODES && lane < nn)
                me = __ldg(g_ebuf + ((size_t)rn << 6) + lane);
        }

        if (r >= N_NODES) {          // pad rows: zeros
            *hrow_hi = make_uint2(0u, 0u);
            *hrow_lo = make_uint2(0u, 0u);
            continue;
        }

        float4 a0 = make_float4(0.f, 0.f, 0.f, 0.f);
        float4 a1 = make_float4(0.f, 0.f, 0.f, 0.f);
        float4 a2 = make_float4(0.f, 0.f, 0.f, 0.f);
        float4 a3 = make_float4(0.f, 0.f, 0.f, 0.f);

        int i = 0;
        for (; i + 8 <= nw; i += 8) {
            uint2 v[8];
            float w[8];
#pragma unroll
            for (int q = 0; q < 8; q++) {
                int   s = __shfl_sync(FULLM, mine.x, i + q);
                w[q] = __int_as_float(__shfl_sync(FULLM, mine.y, i + q));
                v[q] = __ldg(g_fh + ((size_t)s << 5) + lane);
            }
            hfma4(w[0], v[0], a0); hfma4(w[1], v[1], a1);
            hfma4(w[2], v[2], a2); hfma4(w[3], v[3], a3);
            hfma4(w[4], v[4], a0); hfma4(w[5], v[5], a1);
            hfma4(w[6], v[6], a2); hfma4(w[7], v[7], a3);
        }
        if (i + 4 <= nw) {
            uint2 v[4];
            float w[4];
#pragma unroll
            for (int q = 0; q < 4; q++) {
                int   s = __shfl_sync(FULLM, mine.x, i + q);
                w[q] = __int_as_float(__shfl_sync(FULLM, mine.y, i + q));
                v[q] = __ldg(g_fh + ((size_t)s << 5) + lane);
            }
            hfma4(w[0], v[0], a0); hfma4(w[1], v[1], a1);
            hfma4(w[2], v[2], a2); hfma4(w[3], v[3], a3);
            i += 4;
        }
        if (i + 2 <= nw) {
            int   s0 = __shfl_sync(FULLM, mine.x, i);
            float w0 = __int_as_float(__shfl_sync(FULLM, mine.y, i));
            int   s1 = __shfl_sync(FULLM, mine.x, i + 1);
            float w1 = __int_as_float(__shfl_sync(FULLM, mine.y, i + 1));
            uint2 v0 = __ldg(g_fh + ((size_t)s0 << 5) + lane);
            uint2 v1 = __ldg(g_fh + ((size_t)s1 << 5) + lane);
            hfma4(w0, v0, a0); hfma4(w1, v1, a1);
            i += 2;
        }
        if (i < nw) {
            int   s0 = __shfl_sync(FULLM, mine.x, i);
            float w0 = __int_as_float(__shfl_sync(FULLM, mine.y, i));
            uint2 v0 = __ldg(g_fh + ((size_t)s0 << 5) + lane);
            hfma4(w0, v0, a2);
        }
        // rare overflow (degree > 32): scalar broadcast path
        for (int j = 32; j < end; j++) {
            int2 e = __ldg(g_ebuf + ((size_t)r << 6) + j);
            uint2 v = __ldg(g_fh + ((size_t)e.x << 5) + lane);
            hfma4(__int_as_float(e.y), v, a3);
        }

        // exact fp32 self term
        float sw = __ldg(selfw + r) + 1.0f;
        float4 fv = __ldg(f4 + r * 32 + lane);
        float hx = fmaf(fv.x, sw, (a0.x + a1.x) + (a2.x + a3.x));
        float hy = fmaf(fv.y, sw, (a0.y + a1.y) + (a2.y + a3.y));
        float hz = fmaf(fv.z, sw, (a0.z + a1.z) + (a2.z + a3.z));
        float hw = fmaf(fv.w, sw, (a0.w + a1.w) + (a2.w + a3.w));

        __nv_bfloat16 bx = __float2bfloat16(hx), by = __float2bfloat16(hy);
        __nv_bfloat16 bz = __float2bfloat16(hz), bw = __float2bfloat16(hw);
        __nv_bfloat16 lx = __float2bfloat16(hx - __bfloat162float(bx));
        __nv_bfloat16 ly = __float2bfloat16(hy - __bfloat162float(by));
        __nv_bfloat16 lz = __float2bfloat16(hz - __bfloat162float(bz));
        __nv_bfloat16 lw = __float2bfloat16(hw - __bfloat162float(bw));

        uint32_t hi01 = ((uint32_t)__bfloat16_as_ushort(by) << 16) | __bfloat16_as_ushort(bx);
        uint32_t hi23 = ((uint32_t)__bfloat16_as_ushort(bw) << 16) | __bfloat16_as_ushort(bz);
        uint32_t lo01 = ((uint32_t)__bfloat16_as_ushort(ly) << 16) | __bfloat16_as_ushort(lx);
        uint32_t lo23 = ((uint32_t)__bfloat16_as_ushort(lw) << 16) | __bfloat16_as_ushort(lz);
        *hrow_hi = make_uint2(hi01, hi23);
        *hrow_lo = make_uint2(lo01, lo23);
    }
    __syncthreads();

    // reset this block's counters for the next launch
    if (warp == 0) {
        int r = Rbase + lane;
        if (r < N_NODES) g_cnt[r] = 0;
        r += 32;
        if (r < N_NODES) g_cnt[r] = 0;
    }

    // ---------------- Phase B: bf16-split HMMA (fragment-packed B) ---------
    const int rowTile = (warp & 3) * 16;        // 0,16,32,48
    const int colBase = (warp >> 2) * 64;       // 0 or 64
    const int ntgBase = colBase >> 3;           // 0 or 8
    const int gid = lane >> 2;                  // 0..7
    const int tig = lane & 3;                   // 0..3

    float acc[8][4];
#pragma unroll
    for (int n = 0; n < 8; n++)
#pragma unroll
        for (int j = 0; j < 4; j++) acc[n][j] = 0.f;

    const int arow = rowTile + (lane & 15);
    const int ahalf = (lane >> 4) * 8;
    const uint32_t ahi_base = smem_u32(Hhi + arow * HS_STRIDE + ahalf);
    const uint32_t alo_base = smem_u32(Hlo + arow * HS_STRIDE + ahalf);

#pragma unroll
    for (int ks = 0; ks < 8; ks++) {            // k-steps of 16
        uint32_t ah0, ah1, ah2, ah3, al0, al1, al2, al3;
        ldmatrix4(ah0, ah1, ah2, ah3, ahi_base + ks * 32);
        ldmatrix4(al0, al1, al2, al3, alo_base + ks * 32);

        const uint2* wh = g_wfh + ((size_t)(ks * 16 + ntgBase) << 5) + lane;
        const uint2* wl = g_wfl + ((size_t)(ks * 16 + ntgBase) << 5) + lane;
#pragma unroll
        for (int nt = 0; nt < 8; nt++) {
            uint2 bh = __ldg(wh + (nt << 5));   // coalesced 256B/warp, L1-hot
            uint2 bl = __ldg(wl + (nt << 5));
            mma16816(acc[nt][0], acc[nt][1], acc[nt][2], acc[nt][3],
                     ah0, ah1, ah2, ah3, bh.x, bh.y);
            mma16816(acc[nt][0], acc[nt][1], acc[nt][2], acc[nt][3],
                     ah0, ah1, ah2, ah3, bl.x, bl.y);
            mma16816(acc[nt][0], acc[nt][1], acc[nt][2], acc[nt][3],
                     al0, al1, al2, al3, bh.x, bh.y);
        }
    }

    // epilogue: bias + store (C frag: rows gid, gid+8; cols tig*2, tig*2+1)
    const int r0 = Rbase + rowTile + gid;
    const int r1 = r0 + 8;
#pragma unroll
    for (int nt = 0; nt < 8; nt++) {
        int c = colBase + nt * 8 + tig * 2;
        float2 bb = *reinterpret_cast<const float2*>(bvec + c);
        if (r0 < N_NODES) {
            float2 o = make_float2(acc[nt][0] + bb.x, acc[nt][1] + bb.y);
            *reinterpret_cast<float2*>(out + (size_t)r0 * F + c) = o;
        }
        if (r1 < N_NODES) {
            float2 o = make_float2(acc[nt][2] + bb.x, acc[nt][3] + bb.y);
            *reinterpret_cast<float2*>(out + (size_t)r1 * F + c) = o;
        }
    }
}

// ===================== launch ==============================================
extern "C" void kernel_launch(void* const* d_in, const int* in_sizes, int n_in,
                              void* d_out, int out_size)
{
    const float* feature = (const float*)d_in[0];
    const float* selfw   = (const float*)d_in[1];
    const float* weight  = (const float*)d_in[2];
    const int*   src     = (const int*)d_in[3];
    const int*   dst     = (const int*)d_in[4];
    const float* W       = (const float*)d_in[5];
    const float* bvec    = (const float*)d_in[6];
    float*       out     = (float*)d_out;

    const int edge_blocks  = (E_EDGES + 255) / 256;   // 3125
    const int fused_blocks = (N_NODES + 63) / 64;     // 782

    bucket_prep_kernel<<<edge_blocks, 256>>>(W, feature, weight, src, dst);
    fused_kernel<<<fused_blocks, 256>>>(feature, selfw, bvec, out);
}